// round 6
// baseline (speedup 1.0000x reference)
#include <cuda_runtime.h>
#include <cuda_fp16.h>
#include <cstdint>

#define H 128
#define DI 64
#define MAX_N 50000
#define MAX_M 20000
#define MAX_E 1000000
#define SCAN_B 512
#define AS_STRIDE 132
#define BS_STRIDE 136
#define FUSED_SMEM ((128 * AS_STRIDE + 2 * 16 * BS_STRIDE) * 4)

// ---------------- scratch (no allocations allowed) ----------------
__device__ __half g_hitem16[MAX_N * H];   // fp16 gather mirror of h_item
__device__ __half g_hpat16 [MAX_M * H];   // fp16 gather mirror of h_pat
__device__ float  g_whi[4 * H * H];
__device__ float  g_wlo[4 * H * H];
__device__ int    g_i32[MAX_E];
__device__ int    g_p32[MAX_E];
__device__ int    g_psrc[MAX_E];
__device__ int    g_isrc[MAX_E];
__device__ int    g_prow[MAX_M + 1];
__device__ int    g_irow[MAX_N + 1];
__device__ int    g_pcur[MAX_M];
__device__ int    g_icur[MAX_N];
__device__ int    g_pcnt[MAX_M];
__device__ int    g_icnt[MAX_N];
__device__ int    g_pbsum[(MAX_M + SCAN_B - 1) / SCAN_B];
__device__ int    g_ibsum[(MAX_N + SCAN_B - 1) / SCAN_B];
__device__ int    g_is64;

// ---------------- detect (block 0) + zero counts (other blocks) ----------------
__global__ void prep_kernel(const unsigned long long* __restrict__ raw, int nsamp,
                            int N_, int M_) {
    if (blockIdx.x == 0) {
        __shared__ int any;
        if (threadIdx.x == 0) any = 0;
        __syncthreads();
        int found = 0;
        for (int i = threadIdx.x; i < nsamp; i += blockDim.x)
            if ((raw[i] >> 32) != 0ULL) found = 1;
        if (found) atomicExch(&any, 1);
        __syncthreads();
        if (threadIdx.x == 0) g_is64 = any ? 0 : 1;
    } else {
        int i = (blockIdx.x - 1) * blockDim.x + threadIdx.x;
        if (i < N_) g_icnt[i] = 0;
        if (i < M_) g_pcnt[i] = 0;
    }
}

__device__ __forceinline__ int load_idx(const void* raw, int e, int is64) {
    return is64 ? (int)((const long long*)raw)[e] : ((const int*)raw)[e];
}

// ---------------- count + narrow indices ----------------
__global__ void count_kernel(const void* __restrict__ iraw,
                             const void* __restrict__ praw, int E) {
    int e = blockIdx.x * blockDim.x + threadIdx.x;
    if (e >= E) return;
    int is64 = g_is64;
    int s = load_idx(iraw, e, is64);
    int d = load_idx(praw, e, is64);
    g_i32[e] = s;
    g_p32[e] = d;
    atomicAdd(&g_icnt[s], 1);
    atomicAdd(&g_pcnt[d], 1);
}

// ---------------- merged per-block reduction of both count arrays ----------------
__global__ void reduce2_kernel(int pblocks, int M_, int N_) {
    __shared__ int sh[SCAN_B];
    const int* cnt;
    int* bsum;
    int n, b;
    if ((int)blockIdx.x < pblocks) { cnt = g_pcnt; bsum = g_pbsum; n = M_; b = blockIdx.x; }
    else { cnt = g_icnt; bsum = g_ibsum; n = N_; b = blockIdx.x - pblocks; }
    int t = threadIdx.x;
    int i = b * SCAN_B + t;
    sh[t] = (i < n) ? cnt[i] : 0;
    __syncthreads();
    for (int s = SCAN_B / 2; s > 0; s >>= 1) {
        if (t < s) sh[t] += sh[t + s];
        __syncthreads();
    }
    if (t == 0) bsum[b] = sh[0];
}

// ---------------- merged exclusive scan of both bsum arrays (grid=2) ----------------
__global__ void scanb2_kernel(int pblocks, int iblocks) {
    __shared__ int sh[1024];
    int* bsum = (blockIdx.x == 0) ? g_pbsum : g_ibsum;
    int nb = (blockIdx.x == 0) ? pblocks : iblocks;
    int t = threadIdx.x;
    int v = (t < nb) ? bsum[t] : 0;
    sh[t] = v;
    __syncthreads();
    for (int off = 1; off < 1024; off <<= 1) {
        int x = (t >= off) ? sh[t - off] : 0;
        __syncthreads();
        sh[t] += x;
        __syncthreads();
    }
    if (t < nb) bsum[t] = sh[t] - v;
}

// ---------------- merged within-block scan -> rowptr + cursor ----------------
__global__ void scanc2_kernel(int pblocks, int M_, int N_, int E) {
    __shared__ int sh[SCAN_B];
    const int* cnt; const int* bsum;
    int* rowptr; int* cursor;
    int n, b;
    if ((int)blockIdx.x < pblocks) {
        cnt = g_pcnt; bsum = g_pbsum; rowptr = g_prow; cursor = g_pcur; n = M_; b = blockIdx.x;
    } else {
        cnt = g_icnt; bsum = g_ibsum; rowptr = g_irow; cursor = g_icur; n = N_; b = blockIdx.x - pblocks;
    }
    int t = threadIdx.x;
    int i = b * SCAN_B + t;
    int v = (i < n) ? cnt[i] : 0;
    sh[t] = v;
    __syncthreads();
    for (int off = 1; off < SCAN_B; off <<= 1) {
        int x = (t >= off) ? sh[t - off] : 0;
        __syncthreads();
        sh[t] += x;
        __syncthreads();
    }
    int excl = sh[t] - v + bsum[b];
    if (i < n) { rowptr[i] = excl; cursor[i] = excl; }
    if (b == 0 && t == 0) rowptr[n] = E;
}

__global__ void place_kernel(int E) {
    int e = blockIdx.x * blockDim.x + threadIdx.x;
    if (e >= E) return;
    int s = g_i32[e];
    int d = g_p32[e];
    g_psrc[atomicAdd(&g_pcur[d], 1)] = s;
    g_isrc[atomicAdd(&g_icur[s], 1)] = d;
}

// ---------------- weight split (all 4 weights, one launch) ----------------
__device__ __forceinline__ uint32_t to_tf32(float x) {
    uint32_t r;
    asm("cvt.rna.tf32.f32 %0, %1;" : "=r"(r) : "f"(x));
    return r;
}

__global__ void wsplit4_kernel(const float* __restrict__ w0, const float* __restrict__ w1,
                               const float* __restrict__ w2, const float* __restrict__ w3) {
    int i = blockIdx.x * blockDim.x + threadIdx.x;   // 0 .. 4*H*H
    int slot = i >> 14;                              // 16384 per slot
    int off = i & 16383;
    if (slot >= 4) return;
    if (slot < 2 && off >= DI * H) return;           // first two are 64x128
    const float* src = (slot == 0) ? w0 : (slot == 1) ? w1 : (slot == 2) ? w2 : w3;
    float w = src[off];
    float h = __uint_as_float(to_tf32(w));
    g_whi[i] = h;
    g_wlo[i] = __uint_as_float(to_tf32(w - h));
}

// ---------------- accumulate helper ----------------
#define ACC8(a, v) { float2 f0_ = __half22float2(*(__half2*)&(v).x); \
                     float2 f1_ = __half22float2(*(__half2*)&(v).y); \
                     (a).x += f0_.x; (a).y += f0_.y; (a).z += f1_.x; (a).w += f1_.y; }

// ---------------- fused aggregate + 3xTF32 GEMM + residual ReLU + mirror ----------------
// phase 1: block gathers msg for its 128 dest rows into smem (fp16 src, fp32 acc)
// phase 2: C = relu(C + relu(msg @ W + b)); writes fp32 C and fp16 mirror
__global__ __launch_bounds__(256)
void fused_kernel(const __half* __restrict__ src,
                  const int* __restrict__ row, const int* __restrict__ ids,
                  const float* __restrict__ Whi, const float* __restrict__ Wlo,
                  const float* __restrict__ bias,
                  float* __restrict__ C, __half* __restrict__ C16, int n) {
    extern __shared__ float sm[];
    float* As  = sm;                          // [128][AS_STRIDE]
    float* BsH = sm + 128 * AS_STRIDE;        // [16][BS_STRIDE]
    float* BsL = BsH + 16 * BS_STRIDE;

    const int tid = threadIdx.x, wid = tid >> 5, lane = tid & 31;
    const int row0 = blockIdx.x * 128;

    // ---- gather phase: warp wid handles rows wid*16 .. +15 ----
    const __half* sp = src + lane * 4;
#pragma unroll 1
    for (int rr = 0; rr < 16; rr++) {
        int r = wid * 16 + rr;
        int gr = row0 + r;
        float4 a0 = make_float4(0.f, 0.f, 0.f, 0.f);
        float4 a1 = make_float4(0.f, 0.f, 0.f, 0.f);
        float4 a2 = make_float4(0.f, 0.f, 0.f, 0.f);
        float4 a3 = make_float4(0.f, 0.f, 0.f, 0.f);
        if (gr < n) {
            int beg = __ldg(row + gr), end = __ldg(row + gr + 1);
            int e = beg;
            for (; e + 3 < end; e += 4) {
                int s0 = __ldg(ids + e), s1 = __ldg(ids + e + 1);
                int s2 = __ldg(ids + e + 2), s3 = __ldg(ids + e + 3);
                uint2 v0 = *(const uint2*)(sp + (size_t)s0 * H);
                uint2 v1 = *(const uint2*)(sp + (size_t)s1 * H);
                uint2 v2 = *(const uint2*)(sp + (size_t)s2 * H);
                uint2 v3 = *(const uint2*)(sp + (size_t)s3 * H);
                ACC8(a0, v0); ACC8(a1, v1); ACC8(a2, v2); ACC8(a3, v3);
            }
            for (; e < end; e++) {
                uint2 v0 = *(const uint2*)(sp + (size_t)__ldg(ids + e) * H);
                ACC8(a0, v0);
            }
            a0.x += a1.x + a2.x + a3.x;
            a0.y += a1.y + a2.y + a3.y;
            a0.z += a1.z + a2.z + a3.z;
            a0.w += a1.w + a2.w + a3.w;
        }
        *(float4*)&As[r * AS_STRIDE + lane * 4] = a0;   // 528B row stride: 16B aligned
    }
    __syncthreads();

    // ---- GEMM phase (A resident in smem) ----
    const int wr = wid >> 1, wc = wid & 1;
    const int l4 = lane >> 2, lm = lane & 3;

    float acc[2][8][4];
#pragma unroll
    for (int mi = 0; mi < 2; mi++)
#pragma unroll
        for (int nj = 0; nj < 8; nj++)
#pragma unroll
            for (int q = 0; q < 4; q++) acc[mi][nj][q] = 0.f;

    for (int k0 = 0; k0 < H; k0 += 16) {
#pragma unroll
        for (int i = 0; i < 2; i++) {
            int f = tid + i * 256;
            int rB = f >> 5, c4 = (f & 31) * 4;
            *(float4*)&BsH[rB * BS_STRIDE + c4] = *(const float4*)(Whi + (size_t)(k0 + rB) * H + c4);
            *(float4*)&BsL[rB * BS_STRIDE + c4] = *(const float4*)(Wlo + (size_t)(k0 + rB) * H + c4);
        }
        __syncthreads();

#pragma unroll
        for (int ks = 0; ks < 2; ks++) {
            const int kb = ks * 8 + lm;        // local B row
            const int ka = k0 + kb;            // As column
            uint32_t ah[2][4], al[2][4];
#pragma unroll
            for (int mi = 0; mi < 2; mi++) {
                int rb = wr * 32 + mi * 16 + l4;
                float av[4];
                av[0] = As[rb * AS_STRIDE + ka];
                av[1] = As[(rb + 8) * AS_STRIDE + ka];
                av[2] = As[rb * AS_STRIDE + ka + 4];
                av[3] = As[(rb + 8) * AS_STRIDE + ka + 4];
#pragma unroll
                for (int q = 0; q < 4; q++) {
                    uint32_t hb = to_tf32(av[q]);
                    ah[mi][q] = hb;
                    al[mi][q] = to_tf32(av[q] - __uint_as_float(hb));
                }
            }
#pragma unroll
            for (int nj = 0; nj < 8; nj++) {
                int nn = wc * 64 + nj * 8 + l4;
                uint32_t bh0 = __float_as_uint(BsH[kb * BS_STRIDE + nn]);
                uint32_t bh1 = __float_as_uint(BsH[(kb + 4) * BS_STRIDE + nn]);
                uint32_t bl0 = __float_as_uint(BsL[kb * BS_STRIDE + nn]);
                uint32_t bl1 = __float_as_uint(BsL[(kb + 4) * BS_STRIDE + nn]);
#pragma unroll
                for (int mi = 0; mi < 2; mi++) {
                    float* d = acc[mi][nj];
#define TMMA(A0,A1,A2,A3,B0,B1) \
    asm volatile("mma.sync.aligned.m16n8k8.row.col.f32.tf32.tf32.f32 " \
        "{%0,%1,%2,%3},{%4,%5,%6,%7},{%8,%9},{%0,%1,%2,%3};" \
        : "+f"(d[0]), "+f"(d[1]), "+f"(d[2]), "+f"(d[3]) \
        : "r"(A0), "r"(A1), "r"(A2), "r"(A3), "r"(B0), "r"(B1))
                    TMMA(ah[mi][0], ah[mi][1], ah[mi][2], ah[mi][3], bh0, bh1);
                    TMMA(al[mi][0], al[mi][1], al[mi][2], al[mi][3], bh0, bh1);
                    TMMA(ah[mi][0], ah[mi][1], ah[mi][2], ah[mi][3], bl0, bl1);
#undef TMMA
                }
            }
        }
        __syncthreads();
    }

    // ---- epilogue: residual + relu + fp16 mirror ----
#pragma unroll
    for (int mi = 0; mi < 2; mi++) {
#pragma unroll
        for (int hh = 0; hh < 2; hh++) {
            int r = row0 + wr * 32 + mi * 16 + l4 + hh * 8;
            if (r >= n) continue;
#pragma unroll
            for (int nj = 0; nj < 8; nj++) {
                int cc = wc * 64 + nj * 8 + lm * 2;
                float x0 = fmaxf(acc[mi][nj][hh * 2 + 0] + __ldg(bias + cc), 0.f);
                float x1 = fmaxf(acc[mi][nj][hh * 2 + 1] + __ldg(bias + cc + 1), 0.f);
                float2 rv = *(const float2*)(C + (size_t)r * H + cc);
                x0 = fmaxf(rv.x + x0, 0.f);
                x1 = fmaxf(rv.y + x1, 0.f);
                *(float2*)(C + (size_t)r * H + cc) = make_float2(x0, x1);
                *(__half2*)(C16 + (size_t)r * H + cc) = __floats2half2_rn(x0, x1);
            }
        }
    }
}

// ---------------- encoder GEMM: C = relu(A[n,K] @ W + b), fp32 A, writes mirror ----------------
template<int K>
__global__ __launch_bounds__(256, 2)
void tgemm_kernel(const float* __restrict__ A,
                  const float* __restrict__ Whi, const float* __restrict__ Wlo,
                  const float* __restrict__ bias, float* __restrict__ C,
                  __half* __restrict__ C16, int n) {
    constexpr int BM = 128, BN = 128, BK = 16;
    __shared__ float As[BM][20];
    __shared__ float BsH[BK][136];
    __shared__ float BsL[BK][136];

    const int tid = threadIdx.x;
    const int wid = tid >> 5, lane = tid & 31;
    const int wr = wid >> 1, wc = wid & 1;
    const int row0 = blockIdx.x * BM;
    const int l4 = lane >> 2, lm = lane & 3;

    float acc[2][8][4];
#pragma unroll
    for (int mi = 0; mi < 2; mi++)
#pragma unroll
        for (int nj = 0; nj < 8; nj++)
#pragma unroll
            for (int q = 0; q < 4; q++) acc[mi][nj][q] = 0.f;

    for (int k0 = 0; k0 < K; k0 += BK) {
#pragma unroll
        for (int i = 0; i < 2; i++) {
            int f = tid + i * 256;
            int r = f >> 2, c4 = (f & 3) * 4;
            int gr = row0 + r;
            float4 v = make_float4(0.f, 0.f, 0.f, 0.f);
            if (gr < n) v = *(const float4*)(A + (size_t)gr * K + k0 + c4);
            *(float4*)&As[r][c4] = v;
        }
#pragma unroll
        for (int i = 0; i < 2; i++) {
            int f = tid + i * 256;
            int r = f >> 5, c4 = (f & 31) * 4;
            *(float4*)&BsH[r][c4] = *(const float4*)(Whi + (size_t)(k0 + r) * BN + c4);
            *(float4*)&BsL[r][c4] = *(const float4*)(Wlo + (size_t)(k0 + r) * BN + c4);
        }
        __syncthreads();

#pragma unroll
        for (int ks = 0; ks < 2; ks++) {
            const int kb = ks * 8 + lm;
            uint32_t ah[2][4], al[2][4];
#pragma unroll
            for (int mi = 0; mi < 2; mi++) {
                int rb = wr * 32 + mi * 16 + l4;
                float av[4];
                av[0] = As[rb][kb];
                av[1] = As[rb + 8][kb];
                av[2] = As[rb][kb + 4];
                av[3] = As[rb + 8][kb + 4];
#pragma unroll
                for (int q = 0; q < 4; q++) {
                    uint32_t hb = to_tf32(av[q]);
                    ah[mi][q] = hb;
                    al[mi][q] = to_tf32(av[q] - __uint_as_float(hb));
                }
            }
#pragma unroll
            for (int nj = 0; nj < 8; nj++) {
                int nn = wc * 64 + nj * 8 + l4;
                uint32_t bh0 = __float_as_uint(BsH[kb][nn]);
                uint32_t bh1 = __float_as_uint(BsH[kb + 4][nn]);
                uint32_t bl0 = __float_as_uint(BsL[kb][nn]);
                uint32_t bl1 = __float_as_uint(BsL[kb + 4][nn]);
#pragma unroll
                for (int mi = 0; mi < 2; mi++) {
                    float* d = acc[mi][nj];
#define TMMA(A0,A1,A2,A3,B0,B1) \
    asm volatile("mma.sync.aligned.m16n8k8.row.col.f32.tf32.tf32.f32 " \
        "{%0,%1,%2,%3},{%4,%5,%6,%7},{%8,%9},{%0,%1,%2,%3};" \
        : "+f"(d[0]), "+f"(d[1]), "+f"(d[2]), "+f"(d[3]) \
        : "r"(A0), "r"(A1), "r"(A2), "r"(A3), "r"(B0), "r"(B1))
                    TMMA(ah[mi][0], ah[mi][1], ah[mi][2], ah[mi][3], bh0, bh1);
                    TMMA(al[mi][0], al[mi][1], al[mi][2], al[mi][3], bh0, bh1);
                    TMMA(ah[mi][0], ah[mi][1], ah[mi][2], ah[mi][3], bl0, bl1);
#undef TMMA
                }
            }
        }
        __syncthreads();
    }

#pragma unroll
    for (int mi = 0; mi < 2; mi++) {
#pragma unroll
        for (int hh = 0; hh < 2; hh++) {
            int r = row0 + wr * 32 + mi * 16 + l4 + hh * 8;
            if (r >= n) continue;
#pragma unroll
            for (int nj = 0; nj < 8; nj++) {
                int cc = wc * 64 + nj * 8 + lm * 2;
                float x0 = fmaxf(acc[mi][nj][hh * 2 + 0] + __ldg(bias + cc), 0.f);
                float x1 = fmaxf(acc[mi][nj][hh * 2 + 1] + __ldg(bias + cc + 1), 0.f);
                *(float2*)(C + (size_t)r * BN + cc) = make_float2(x0, x1);
                *(__half2*)(C16 + (size_t)r * BN + cc) = __floats2half2_rn(x0, x1);
            }
        }
    }
}

// ---------------- launch ----------------
extern "C" void kernel_launch(void* const* d_in, const int* in_sizes, int n_in,
                              void* d_out, int out_size) {
    const float* item_feat = (const float*)d_in[0];
    const float* pat_feat  = (const float*)d_in[1];
    const void*  iidx_raw  = d_in[2];
    const void*  pidx_raw  = d_in[3];
    const float* W_item = (const float*)d_in[4];
    const float* b_item = (const float*)d_in[5];
    const float* W_pat  = (const float*)d_in[6];
    const float* b_pat  = (const float*)d_in[7];
    const float* W_i2p  = (const float*)d_in[8];
    const float* b_i2p  = (const float*)d_in[9];
    const float* W_p2i  = (const float*)d_in[10];
    const float* b_p2i  = (const float*)d_in[11];

    const int N_ = in_sizes[0] / DI;
    const int M_ = in_sizes[1] / DI;
    const int E_ = in_sizes[2];

    float* h_item = (float*)d_out;
    float* h_pat  = (float*)d_out + (size_t)N_ * H;

    void* p;
    cudaGetSymbolAddress(&p, g_hitem16); __half* hitem16 = (__half*)p;
    cudaGetSymbolAddress(&p, g_hpat16);  __half* hpat16  = (__half*)p;
    cudaGetSymbolAddress(&p, g_whi);     float*  whi     = (float*)p;
    cudaGetSymbolAddress(&p, g_wlo);     float*  wlo     = (float*)p;
    cudaGetSymbolAddress(&p, g_psrc);    int* psrc = (int*)p;
    cudaGetSymbolAddress(&p, g_isrc);    int* isrc = (int*)p;
    cudaGetSymbolAddress(&p, g_prow);    int* prow = (int*)p;
    cudaGetSymbolAddress(&p, g_irow);    int* irow = (int*)p;

    float* wi_hi  = whi;                float* wi_lo  = wlo;
    float* wp_hi  = whi + 1 * H * H;    float* wp_lo  = wlo + 1 * H * H;
    float* w2p_hi = whi + 2 * H * H;    float* w2p_lo = wlo + 2 * H * H;
    float* w2i_hi = whi + 3 * H * H;    float* w2i_lo = wlo + 3 * H * H;

    static int smem_set = 0;
    if (!smem_set) {
        cudaFuncSetAttribute(fused_kernel, cudaFuncAttributeMaxDynamicSharedMemorySize,
                             FUSED_SMEM);
        smem_set = 1;
    }

    const int pblocks = (M_ + SCAN_B - 1) / SCAN_B;
    const int iblocks = (N_ + SCAN_B - 1) / SCAN_B;
    const int maxnm = (N_ > M_) ? N_ : M_;

    // ---- CSR build ----
    int nsamp = E_ / 2 < 1024 ? E_ / 2 : 1024;
    prep_kernel<<<1 + (maxnm + 255) / 256, 256>>>((const unsigned long long*)iidx_raw,
                                                  nsamp, N_, M_);
    count_kernel<<<(E_ + 255) / 256, 256>>>(iidx_raw, pidx_raw, E_);
    reduce2_kernel<<<pblocks + iblocks, SCAN_B>>>(pblocks, M_, N_);
    scanb2_kernel<<<2, 1024>>>(pblocks, iblocks);
    scanc2_kernel<<<pblocks + iblocks, SCAN_B>>>(pblocks, M_, N_, E_);
    place_kernel<<<(E_ + 255) / 256, 256>>>(E_);

    // ---- weight splits (one launch) ----
    wsplit4_kernel<<<(4 * H * H + 255) / 256, 256>>>(W_item, W_pat, W_i2p, W_p2i);

    // ---- encoders (fp32 in, fp32 state + fp16 mirror out) ----
    tgemm_kernel<DI><<<(N_ + 127) / 128, 256>>>(item_feat, wi_hi, wi_lo, b_item, h_item, hitem16, N_);
    tgemm_kernel<DI><<<(M_ + 127) / 128, 256>>>(pat_feat,  wp_hi, wp_lo, b_pat,  h_pat,  hpat16,  M_);

    // ---- rounds: fused gather + GEMM + residual ----
    const int pg = (M_ + 127) / 128;
    const int ig = (N_ + 127) / 128;
    for (int r = 0; r < 2; r++) {
        fused_kernel<<<pg, 256, FUSED_SMEM>>>(hitem16, prow, psrc,
                                              w2p_hi, w2p_lo, b_i2p, h_pat, hpat16, M_);
        fused_kernel<<<ig, 256, FUSED_SMEM>>>(hpat16, irow, isrc,
                                              w2i_hi, w2i_lo, b_p2i, h_item, hitem16, N_);
    }
}

// round 7
// speedup vs baseline: 1.5131x; 1.5131x over previous
#include <cuda_runtime.h>
#include <cstdint>

#define H 128
#define DI 64
#define MAX_N 50000
#define MAX_M 20000
#define MAX_E 1000000
#define SCAN_B 512

// ---------------- scratch (no allocations allowed) ----------------
__device__ float  g_pmsg[MAX_M * H];
__device__ float  g_imsg[MAX_N * H];
__device__ int    g_i32[MAX_E];
__device__ int    g_p32[MAX_E];
__device__ int    g_psrc[MAX_E];
__device__ int    g_isrc[MAX_E];
__device__ int    g_prow[MAX_M + 1];
__device__ int    g_irow[MAX_N + 1];
__device__ int    g_pcur[MAX_M];
__device__ int    g_icur[MAX_N];
__device__ int    g_pcnt[MAX_M];
__device__ int    g_icnt[MAX_N];
__device__ int    g_pbsum[(MAX_M + SCAN_B - 1) / SCAN_B];
__device__ int    g_ibsum[(MAX_N + SCAN_B - 1) / SCAN_B];

// ---------------- zero both count arrays ----------------
__global__ void zero2_kernel(int N_, int M_) {
    int i = blockIdx.x * blockDim.x + threadIdx.x;
    if (i < N_) g_icnt[i] = 0;
    if (i < M_) g_pcnt[i] = 0;
}

// ---------------- count + narrow (detect int64-vs-int32 inline, per block) ----------------
// int64 indices < 2^32 => every high 32-bit word is 0; int32 index data makes the
// sampled "high words" be real indices (nonzero w.h.p.). Every block samples the
// SAME first 64 words -> identical, deterministic verdict.
__global__ void count_kernel(const void* __restrict__ iraw,
                             const void* __restrict__ praw, int E) {
    __shared__ int s_is64;
    int t = threadIdx.x;
    if (t < 32) {
        int nsamp = (E / 2 < 64) ? E / 2 : 64;
        unsigned long long hi = 0;
        for (int i = t; i < nsamp; i += 32)
            hi |= (((const unsigned long long*)iraw)[i] >> 32);
        unsigned any = __ballot_sync(0xFFFFFFFFu, hi != 0ULL);
        if (t == 0) s_is64 = (any == 0u) ? 1 : 0;
    }
    __syncthreads();
    int is64 = s_is64;
    int e = blockIdx.x * blockDim.x + t;
    if (e >= E) return;
    int s = is64 ? (int)((const long long*)iraw)[e] : ((const int*)iraw)[e];
    int d = is64 ? (int)((const long long*)praw)[e] : ((const int*)praw)[e];
    g_i32[e] = s;
    g_p32[e] = d;
    atomicAdd(&g_icnt[s], 1);
    atomicAdd(&g_pcnt[d], 1);
}

// ---------------- merged per-block reduction of both count arrays ----------------
__global__ void reduce2_kernel(int pblocks, int M_, int N_) {
    __shared__ int sh[SCAN_B];
    const int* cnt; int* bsum; int n, b;
    if ((int)blockIdx.x < pblocks) { cnt = g_pcnt; bsum = g_pbsum; n = M_; b = blockIdx.x; }
    else { cnt = g_icnt; bsum = g_ibsum; n = N_; b = blockIdx.x - pblocks; }
    int t = threadIdx.x;
    int i = b * SCAN_B + t;
    sh[t] = (i < n) ? cnt[i] : 0;
    __syncthreads();
    for (int s = SCAN_B / 2; s > 0; s >>= 1) {
        if (t < s) sh[t] += sh[t + s];
        __syncthreads();
    }
    if (t == 0) bsum[b] = sh[0];
}

// ---------------- merged exclusive scan of both bsum arrays (grid=2) ----------------
__global__ void scanb2_kernel(int pblocks, int iblocks) {
    __shared__ int sh[1024];
    int* bsum = (blockIdx.x == 0) ? g_pbsum : g_ibsum;
    int nb = (blockIdx.x == 0) ? pblocks : iblocks;
    int t = threadIdx.x;
    int v = (t < nb) ? bsum[t] : 0;
    sh[t] = v;
    __syncthreads();
    for (int off = 1; off < 1024; off <<= 1) {
        int x = (t >= off) ? sh[t - off] : 0;
        __syncthreads();
        sh[t] += x;
        __syncthreads();
    }
    if (t < nb) bsum[t] = sh[t] - v;
}

// ---------------- merged within-block scan -> rowptr + cursor ----------------
__global__ void scanc2_kernel(int pblocks, int M_, int N_, int E) {
    __shared__ int sh[SCAN_B];
    const int* cnt; const int* bsum; int* rowptr; int* cursor; int n, b;
    if ((int)blockIdx.x < pblocks) {
        cnt = g_pcnt; bsum = g_pbsum; rowptr = g_prow; cursor = g_pcur; n = M_; b = blockIdx.x;
    } else {
        cnt = g_icnt; bsum = g_ibsum; rowptr = g_irow; cursor = g_icur; n = N_; b = blockIdx.x - pblocks;
    }
    int t = threadIdx.x;
    int i = b * SCAN_B + t;
    int v = (i < n) ? cnt[i] : 0;
    sh[t] = v;
    __syncthreads();
    for (int off = 1; off < SCAN_B; off <<= 1) {
        int x = (t >= off) ? sh[t - off] : 0;
        __syncthreads();
        sh[t] += x;
        __syncthreads();
    }
    int excl = sh[t] - v + bsum[b];
    if (i < n) { rowptr[i] = excl; cursor[i] = excl; }
    if (b == 0 && t == 0) rowptr[n] = E;
}

__global__ void place_kernel(int E) {
    int e = blockIdx.x * blockDim.x + threadIdx.x;
    if (e >= E) return;
    int s = g_i32[e];
    int d = g_p32[e];
    g_psrc[atomicAdd(&g_pcur[d], 1)] = s;
    g_isrc[atomicAdd(&g_icur[s], 1)] = d;
}

// ---------------- segmented gather-reduce (fp32, one warp per dest row) ----------------
__global__ __launch_bounds__(256)
void aggregate_kernel(const float* __restrict__ src, float* __restrict__ dst,
                      const int* __restrict__ row, const int* __restrict__ srcids,
                      int ndst) {
    int w = (int)((blockIdx.x * blockDim.x + threadIdx.x) >> 5);
    if (w >= ndst) return;
    int lane = threadIdx.x & 31;
    int beg = __ldg(row + w);
    int end = __ldg(row + w + 1);
    const float* sp = src + lane * 4;

    float4 a0 = make_float4(0.f, 0.f, 0.f, 0.f);
    float4 a1 = make_float4(0.f, 0.f, 0.f, 0.f);
    float4 a2 = make_float4(0.f, 0.f, 0.f, 0.f);
    float4 a3 = make_float4(0.f, 0.f, 0.f, 0.f);
    int e = beg;
    for (; e + 3 < end; e += 4) {
        int s0 = __ldg(srcids + e),     s1 = __ldg(srcids + e + 1);
        int s2 = __ldg(srcids + e + 2), s3 = __ldg(srcids + e + 3);
        float4 v0 = *(const float4*)(sp + (size_t)s0 * H);
        float4 v1 = *(const float4*)(sp + (size_t)s1 * H);
        float4 v2 = *(const float4*)(sp + (size_t)s2 * H);
        float4 v3 = *(const float4*)(sp + (size_t)s3 * H);
        a0.x += v0.x; a0.y += v0.y; a0.z += v0.z; a0.w += v0.w;
        a1.x += v1.x; a1.y += v1.y; a1.z += v1.z; a1.w += v1.w;
        a2.x += v2.x; a2.y += v2.y; a2.z += v2.z; a2.w += v2.w;
        a3.x += v3.x; a3.y += v3.y; a3.z += v3.z; a3.w += v3.w;
    }
    for (; e < end; e++) {
        float4 v0 = *(const float4*)(sp + (size_t)__ldg(srcids + e) * H);
        a0.x += v0.x; a0.y += v0.y; a0.z += v0.z; a0.w += v0.w;
    }
    a0.x += (a1.x + a2.x) + a3.x;
    a0.y += (a1.y + a2.y) + a3.y;
    a0.z += (a1.z + a2.z) + a3.z;
    a0.w += (a1.w + a2.w) + a3.w;
    *(float4*)(dst + (size_t)w * H + lane * 4) = a0;
}

// ---------------- 3xTF32 GEMM body (W split in-register while filling smem) ----------------
__device__ __forceinline__ uint32_t to_tf32(float x) {
    uint32_t r;
    asm("cvt.rna.tf32.f32 %0, %1;" : "=r"(r) : "f"(x));
    return r;
}

template<int K, bool FUSED>
__device__ __forceinline__
void tgemm_body(const float* __restrict__ A, const float* __restrict__ W,
                const float* __restrict__ bias, float* __restrict__ C,
                int n, int brow) {
    constexpr int BM = 128, BN = 128, BK = 16;
    __shared__ float As[BM][20];
    __shared__ float BsH[BK][136];
    __shared__ float BsL[BK][136];

    const int tid = threadIdx.x;
    const int wid = tid >> 5, lane = tid & 31;
    const int wr = wid >> 1, wc = wid & 1;
    const int row0 = brow * BM;
    const int l4 = lane >> 2, lm = lane & 3;

    float acc[2][8][4];
#pragma unroll
    for (int mi = 0; mi < 2; mi++)
#pragma unroll
        for (int nj = 0; nj < 8; nj++)
#pragma unroll
            for (int q = 0; q < 4; q++) acc[mi][nj][q] = 0.f;

    for (int k0 = 0; k0 < K; k0 += BK) {
#pragma unroll
        for (int i = 0; i < 2; i++) {
            int f = tid + i * 256;
            int r = f >> 2, c4 = (f & 3) * 4;
            int gr = row0 + r;
            float4 v = make_float4(0.f, 0.f, 0.f, 0.f);
            if (gr < n) v = *(const float4*)(A + (size_t)gr * K + k0 + c4);
            *(float4*)&As[r][c4] = v;
        }
#pragma unroll
        for (int i = 0; i < 2; i++) {
            int f = tid + i * 256;
            int r = f >> 5, c4 = (f & 31) * 4;
            float4 w = *(const float4*)(W + (size_t)(k0 + r) * BN + c4);
            float4 h, lo;
            h.x = __uint_as_float(to_tf32(w.x)); lo.x = w.x - h.x;
            h.y = __uint_as_float(to_tf32(w.y)); lo.y = w.y - h.y;
            h.z = __uint_as_float(to_tf32(w.z)); lo.z = w.z - h.z;
            h.w = __uint_as_float(to_tf32(w.w)); lo.w = w.w - h.w;
            *(float4*)&BsH[r][c4] = h;
            *(float4*)&BsL[r][c4] = lo;
        }
        __syncthreads();

#pragma unroll
        for (int ks = 0; ks < 2; ks++) {
            const int kb = ks * 8 + lm;
            uint32_t ah[2][4], al[2][4];
#pragma unroll
            for (int mi = 0; mi < 2; mi++) {
                int rb = wr * 32 + mi * 16 + l4;
                float av[4];
                av[0] = As[rb][kb];
                av[1] = As[rb + 8][kb];
                av[2] = As[rb][kb + 4];
                av[3] = As[rb + 8][kb + 4];
#pragma unroll
                for (int q = 0; q < 4; q++) {
                    uint32_t hb = to_tf32(av[q]);
                    ah[mi][q] = hb;
                    al[mi][q] = to_tf32(av[q] - __uint_as_float(hb));
                }
            }
#pragma unroll
            for (int nj = 0; nj < 8; nj++) {
                int nn = wc * 64 + nj * 8 + l4;
                uint32_t bh0 = __float_as_uint(BsH[kb][nn]);
                uint32_t bh1 = __float_as_uint(BsH[kb + 4][nn]);
                uint32_t bl0 = __float_as_uint(BsL[kb][nn]);
                uint32_t bl1 = __float_as_uint(BsL[kb + 4][nn]);
#pragma unroll
                for (int mi = 0; mi < 2; mi++) {
                    float* d = acc[mi][nj];
#define TMMA(A0,A1,A2,A3,B0,B1) \
    asm volatile("mma.sync.aligned.m16n8k8.row.col.f32.tf32.tf32.f32 " \
        "{%0,%1,%2,%3},{%4,%5,%6,%7},{%8,%9},{%0,%1,%2,%3};" \
        : "+f"(d[0]), "+f"(d[1]), "+f"(d[2]), "+f"(d[3]) \
        : "r"(A0), "r"(A1), "r"(A2), "r"(A3), "r"(B0), "r"(B1))
                    TMMA(ah[mi][0], ah[mi][1], ah[mi][2], ah[mi][3], bh0, bh1);
                    TMMA(al[mi][0], al[mi][1], al[mi][2], al[mi][3], bh0, bh1);
                    TMMA(ah[mi][0], ah[mi][1], ah[mi][2], ah[mi][3], bl0, bl1);
#undef TMMA
                }
            }
        }
        __syncthreads();
    }

#pragma unroll
    for (int mi = 0; mi < 2; mi++) {
#pragma unroll
        for (int hh = 0; hh < 2; hh++) {
            int r = row0 + wr * 32 + mi * 16 + l4 + hh * 8;
            if (r >= n) continue;
#pragma unroll
            for (int nj = 0; nj < 8; nj++) {
                int cc = wc * 64 + nj * 8 + lm * 2;
                float x0 = fmaxf(acc[mi][nj][hh * 2 + 0] + __ldg(bias + cc), 0.f);
                float x1 = fmaxf(acc[mi][nj][hh * 2 + 1] + __ldg(bias + cc + 1), 0.f);
                if (FUSED) {
                    float2 rv = *(const float2*)(C + (size_t)r * BN + cc);
                    x0 = fmaxf(rv.x + x0, 0.f);
                    x1 = fmaxf(rv.y + x1, 0.f);
                }
                *(float2*)(C + (size_t)r * BN + cc) = make_float2(x0, x1);
            }
        }
    }
}

// round GEMM (fused residual)
__global__ __launch_bounds__(256, 2)
void tgemm_fused_kernel(const float* __restrict__ A, const float* __restrict__ W,
                        const float* __restrict__ bias, float* __restrict__ C, int n) {
    tgemm_body<H, true>(A, W, bias, C, n, blockIdx.x);
}

// both encoders in one launch (K = DI for both)
__global__ __launch_bounds__(256, 2)
void enc2_kernel(const float* __restrict__ A0, const float* __restrict__ W0,
                 const float* __restrict__ b0, float* __restrict__ C0, int n0, int g0,
                 const float* __restrict__ A1, const float* __restrict__ W1,
                 const float* __restrict__ b1, float* __restrict__ C1, int n1) {
    if ((int)blockIdx.x < g0)
        tgemm_body<DI, false>(A0, W0, b0, C0, n0, blockIdx.x);
    else
        tgemm_body<DI, false>(A1, W1, b1, C1, n1, blockIdx.x - g0);
}

// ---------------- launch ----------------
extern "C" void kernel_launch(void* const* d_in, const int* in_sizes, int n_in,
                              void* d_out, int out_size) {
    const float* item_feat = (const float*)d_in[0];
    const float* pat_feat  = (const float*)d_in[1];
    const void*  iidx_raw  = d_in[2];
    const void*  pidx_raw  = d_in[3];
    const float* W_item = (const float*)d_in[4];
    const float* b_item = (const float*)d_in[5];
    const float* W_pat  = (const float*)d_in[6];
    const float* b_pat  = (const float*)d_in[7];
    const float* W_i2p  = (const float*)d_in[8];
    const float* b_i2p  = (const float*)d_in[9];
    const float* W_p2i  = (const float*)d_in[10];
    const float* b_p2i  = (const float*)d_in[11];

    const int N_ = in_sizes[0] / DI;
    const int M_ = in_sizes[1] / DI;
    const int E_ = in_sizes[2];

    float* h_item = (float*)d_out;
    float* h_pat  = (float*)d_out + (size_t)N_ * H;

    void* p;
    cudaGetSymbolAddress(&p, g_pmsg); float* pmsg = (float*)p;
    cudaGetSymbolAddress(&p, g_imsg); float* imsg = (float*)p;
    cudaGetSymbolAddress(&p, g_psrc); int* psrc = (int*)p;
    cudaGetSymbolAddress(&p, g_isrc); int* isrc = (int*)p;
    cudaGetSymbolAddress(&p, g_prow); int* prow = (int*)p;
    cudaGetSymbolAddress(&p, g_irow); int* irow = (int*)p;

    const int pblocks = (M_ + SCAN_B - 1) / SCAN_B;
    const int iblocks = (N_ + SCAN_B - 1) / SCAN_B;
    const int maxnm = (N_ > M_) ? N_ : M_;

    // ---- CSR build ----
    zero2_kernel<<<(maxnm + 255) / 256, 256>>>(N_, M_);
    count_kernel<<<(E_ + 255) / 256, 256>>>(iidx_raw, pidx_raw, E_);
    reduce2_kernel<<<pblocks + iblocks, SCAN_B>>>(pblocks, M_, N_);
    scanb2_kernel<<<2, 1024>>>(pblocks, iblocks);
    scanc2_kernel<<<pblocks + iblocks, SCAN_B>>>(pblocks, M_, N_, E_);
    place_kernel<<<(E_ + 255) / 256, 256>>>(E_);

    // ---- encoders (one launch, K=64 both) ----
    const int gN = (N_ + 127) / 128;
    const int gM = (M_ + 127) / 128;
    enc2_kernel<<<gN + gM, 256>>>(item_feat, W_item, b_item, h_item, N_, gN,
                                  pat_feat,  W_pat,  b_pat,  h_pat,  M_);

    const int pagg_blocks = (M_ * 32 + 255) / 256;
    const int iagg_blocks = (N_ * 32 + 255) / 256;

    for (int r = 0; r < 2; r++) {
        // item -> pattern
        aggregate_kernel<<<pagg_blocks, 256>>>(h_item, pmsg, prow, psrc, M_);
        tgemm_fused_kernel<<<gM, 256>>>(pmsg, W_i2p, b_i2p, h_pat, M_);
        // pattern -> item
        aggregate_kernel<<<iagg_blocks, 256>>>(h_pat, imsg, irow, isrc, N_);
        tgemm_fused_kernel<<<gN, 256>>>(imsg, W_p2i, b_p2i, h_item, N_);
    }
}